// round 2
// baseline (speedup 1.0000x reference)
#include <cuda_runtime.h>

#define N_NODES 50000
#define N_EDGES 800000
#define C_DIM 64
#define HEADS 3
#define HC 192
#define EA_DIM 16
#define NEG_SLOPE 0.2f

// ---------------- scratch (device globals; no allocation in kernel_launch) ----
__device__ float g_xproj[N_NODES * HC];        // x @ W_node
__device__ float g_s0[N_NODES * HEADS];        // per-node dot with att[:,0]
__device__ float g_s2[N_NODES * HEADS];        // per-node dot with att[:,2]
__device__ float g_q[HEADS * EA_DIM];          // W_edge^T folded with att[:,1]
__device__ float g_alpha[N_EDGES * HEADS];     // leaky-relu'd logits
__device__ int   g_deg[N_NODES];
__device__ int   g_rowptr[N_NODES + 1];
__device__ int   g_cursor[N_NODES];
__device__ int   g_eids[N_EDGES];
__device__ float g_aggr[N_NODES * HC];

// ---------------- f32x2 helpers ----------------------------------------------
__device__ __forceinline__ unsigned long long pk2(float lo, float hi) {
    unsigned long long r;
    asm("mov.b64 %0, {%1,%2};" : "=l"(r) : "f"(lo), "f"(hi));
    return r;
}
__device__ __forceinline__ void fma2(unsigned long long& d,
                                     unsigned long long a,
                                     unsigned long long b) {
    asm("fma.rn.f32x2 %0, %1, %2, %0;" : "+l"(d) : "l"(a), "l"(b));
}
__device__ __forceinline__ float hsum2(unsigned long long v) {
    float lo, hi;
    asm("mov.b64 {%0,%1}, %2;" : "=f"(lo), "=f"(hi) : "l"(v));
    return lo + hi;
}

// ---------------- K0: zero degree histogram ----------------------------------
__global__ void k_zero() {
    int i = blockIdx.x * blockDim.x + threadIdx.x;
    if (i < N_NODES) g_deg[i] = 0;
}

// ---------------- K1: x_proj = x @ W_node  (block: 8 nodes x 192 channels) ---
__global__ void k_proj(const float* __restrict__ x, const float* __restrict__ Wn) {
    __shared__ __align__(16) float xT[64 * 8];  // transposed x tile [k][n]
    int n0 = blockIdx.x * 8;
    int t = threadIdx.x;  // 0..191 = output channel
    for (int i = t; i < 8 * 64; i += 192) {
        int n = i >> 6, k = i & 63;
        xT[k * 8 + n] = x[(n0 + n) * 64 + k];
    }
    __syncthreads();
    float acc[8];
#pragma unroll
    for (int n = 0; n < 8; n++) acc[n] = 0.f;
#pragma unroll 4
    for (int k = 0; k < 64; k++) {
        float wv = Wn[k * HC + t];
        const float4* xr = reinterpret_cast<const float4*>(xT + k * 8);
        float4 xa = xr[0], xb = xr[1];
        acc[0] += wv * xa.x; acc[1] += wv * xa.y;
        acc[2] += wv * xa.z; acc[3] += wv * xa.w;
        acc[4] += wv * xb.x; acc[5] += wv * xb.y;
        acc[6] += wv * xb.z; acc[7] += wv * xb.w;
    }
#pragma unroll
    for (int n = 0; n < 8; n++) g_xproj[(n0 + n) * HC + t] = acc[n];
}

// ---------------- K2: per-node s0, s2 (one block of 192 per node) ------------
__global__ void k_s(const float* __restrict__ att) {
    int i = blockIdx.x;
    int t = threadIdx.x;              // 0..191
    int h = t >> 6, c = t & 63;
    float v = g_xproj[i * HC + t];
    float p0 = v * att[h * HC + c];
    float p2 = v * att[h * HC + 128 + c];
#pragma unroll
    for (int o = 16; o; o >>= 1) {
        p0 += __shfl_xor_sync(0xffffffffu, p0, o);
        p2 += __shfl_xor_sync(0xffffffffu, p2, o);
    }
    __shared__ float sr[6][2];
    int w = t >> 5, lane = t & 31;
    if (lane == 0) { sr[w][0] = p0; sr[w][1] = p2; }
    __syncthreads();
    if (t < 3) {
        g_s0[i * 3 + t] = sr[2 * t][0] + sr[2 * t + 1][0];
        g_s2[i * 3 + t] = sr[2 * t][1] + sr[2 * t + 1][1];
    }
}

// ---------------- K3: q[h,k] = sum_c W_edge[k, h*64+c] * att[h, 1, c] --------
__global__ void k_q(const float* __restrict__ We, const float* __restrict__ att) {
    int t = threadIdx.x;
    if (t < 48) {
        int h = t / 16, k = t % 16;
        float s = 0.f;
        for (int c = 0; c < 64; c++)
            s += We[k * HC + h * 64 + c] * att[h * HC + 64 + c];
        g_q[h * EA_DIM + k] = s;
    }
}

// ---------------- K4: per-edge alpha + degree histogram ----------------------
__global__ void k_alpha(const int* __restrict__ ei,
                        const float* __restrict__ eattr) {
    __shared__ float qs[48];
    if (threadIdx.x < 48) qs[threadIdx.x] = g_q[threadIdx.x];
    __syncthreads();
    int e = blockIdx.x * blockDim.x + threadIdx.x;
    if (e >= N_EDGES) return;
    int src = ei[e];
    int dst = ei[N_EDGES + e];
    const float4* ap = reinterpret_cast<const float4*>(eattr) + (size_t)e * 4;
    float4 a0 = ap[0], a1 = ap[1], a2 = ap[2], a3 = ap[3];
#pragma unroll
    for (int h = 0; h < 3; h++) {
        const float* q = qs + h * 16;
        float s = g_s0[dst * 3 + h] + g_s2[src * 3 + h];
        s += a0.x * q[0]  + a0.y * q[1]  + a0.z * q[2]  + a0.w * q[3];
        s += a1.x * q[4]  + a1.y * q[5]  + a1.z * q[6]  + a1.w * q[7];
        s += a2.x * q[8]  + a2.y * q[9]  + a2.z * q[10] + a2.w * q[11];
        s += a3.x * q[12] + a3.y * q[13] + a3.z * q[14] + a3.w * q[15];
        s = (s >= 0.f) ? s : NEG_SLOPE * s;   // leaky relu
        g_alpha[e * 3 + h] = s;
    }
    atomicAdd(&g_deg[dst], 1);
}

// ---------------- K5: single-block exclusive scan (rowptr, cursor) -----------
__global__ void k_scan() {
    __shared__ int s[1024];
    __shared__ int carry_s;
    int t = threadIdx.x;
    if (t == 0) carry_s = 0;
    __syncthreads();
    for (int base = 0; base < N_NODES; base += 1024) {
        int i = base + t;
        int v = (i < N_NODES) ? g_deg[i] : 0;
        s[t] = v;
        __syncthreads();
        for (int off = 1; off < 1024; off <<= 1) {
            int xv = 0;
            if (t >= off) xv = s[t - off];
            __syncthreads();
            if (t >= off) s[t] += xv;
            __syncthreads();
        }
        int incl = s[t];
        int excl = incl - v + carry_s;
        if (i < N_NODES) { g_rowptr[i] = excl; g_cursor[i] = excl; }
        __syncthreads();
        if (t == 1023) carry_s += incl;
        __syncthreads();
    }
    if (t == 0) g_rowptr[N_NODES] = carry_s;
}

// ---------------- K6: scatter edge ids into CSR ------------------------------
__global__ void k_scatter(const int* __restrict__ ei) {
    int e = blockIdx.x * blockDim.x + threadIdx.x;
    if (e >= N_EDGES) return;
    int dst = ei[N_EDGES + e];
    int pos = atomicAdd(&g_cursor[dst], 1);
    g_eids[pos] = e;
}

// ---------------- K7: per-node softmax + message aggregation -----------------
// block = 96 threads (3 warps), thread t owns channels (2t, 2t+1); head = t>>5.
// e_ij recomputed on the fly from edge_attr (smem) and W_edge (packed regs)
// using fma.rn.f32x2 (pairs over k).
#define CHUNK 32
__global__ void k_aggr(const int* __restrict__ ei,
                       const float* __restrict__ eattr,
                       const float* __restrict__ We) {
    int t = threadIdx.x;           // 0..95
    int wid = t >> 5, lane = t & 31;
    int c0 = 2 * t, c1 = 2 * t + 1;
    int h = t >> 5;                // head of channels c0,c1

    // per-thread weight packs: Wp[m] = (We[2m, c], We[2m+1, c])
    unsigned long long Wp0[8], Wp1[8];
#pragma unroll
    for (int m = 0; m < 8; m++) {
        Wp0[m] = pk2(We[(2 * m) * HC + c0], We[(2 * m + 1) * HC + c0]);
        Wp1[m] = pk2(We[(2 * m) * HC + c1], We[(2 * m + 1) * HC + c1]);
    }

    __shared__ float s_m[3], s_inv[3];
    __shared__ float s_red[3][3];
    __shared__ int   s_src[CHUNK];
    __shared__ float s_w[CHUNK * 3];
    __shared__ __align__(16) float s_ea[CHUNK * 16];

    for (int i = blockIdx.x; i < N_NODES; i += gridDim.x) {
        int rs = g_rowptr[i], re = g_rowptr[i + 1];

        // ---- phase A1: per-head max over incoming edges
        float lm0 = -1e30f, lm1 = -1e30f, lm2 = -1e30f;
        for (int p = rs + t; p < re; p += 96) {
            int eid = g_eids[p];
            lm0 = fmaxf(lm0, g_alpha[eid * 3 + 0]);
            lm1 = fmaxf(lm1, g_alpha[eid * 3 + 1]);
            lm2 = fmaxf(lm2, g_alpha[eid * 3 + 2]);
        }
#pragma unroll
        for (int o = 16; o; o >>= 1) {
            lm0 = fmaxf(lm0, __shfl_xor_sync(0xffffffffu, lm0, o));
            lm1 = fmaxf(lm1, __shfl_xor_sync(0xffffffffu, lm1, o));
            lm2 = fmaxf(lm2, __shfl_xor_sync(0xffffffffu, lm2, o));
        }
        if (lane == 0) { s_red[wid][0] = lm0; s_red[wid][1] = lm1; s_red[wid][2] = lm2; }
        __syncthreads();
        if (t < 3) s_m[t] = fmaxf(fmaxf(s_red[0][t], s_red[1][t]), s_red[2][t]);
        __syncthreads();
        float m0 = s_m[0], m1 = s_m[1], m2 = s_m[2];

        // ---- phase A2: per-head exp-sum
        float z0 = 0.f, z1 = 0.f, z2 = 0.f;
        for (int p = rs + t; p < re; p += 96) {
            int eid = g_eids[p];
            z0 += __expf(g_alpha[eid * 3 + 0] - m0);
            z1 += __expf(g_alpha[eid * 3 + 1] - m1);
            z2 += __expf(g_alpha[eid * 3 + 2] - m2);
        }
#pragma unroll
        for (int o = 16; o; o >>= 1) {
            z0 += __shfl_xor_sync(0xffffffffu, z0, o);
            z1 += __shfl_xor_sync(0xffffffffu, z1, o);
            z2 += __shfl_xor_sync(0xffffffffu, z2, o);
        }
        if (lane == 0) { s_red[wid][0] = z0; s_red[wid][1] = z1; s_red[wid][2] = z2; }
        __syncthreads();
        if (t < 3)
            s_inv[t] = 1.f / (s_red[0][t] + s_red[1][t] + s_red[2][t] + 1e-16f);
        __syncthreads();

        // ---- phase B: weighted message accumulation (chunks of 32 edges)
        unsigned long long acc0 = 0ull, acc1 = 0ull;
        for (int base = rs; base < re; base += CHUNK) {
            int nthis = min(CHUNK, re - base);
            if (t < nthis) {
                int eid = g_eids[base + t];
                s_src[t] = ei[eid];
#pragma unroll
                for (int hh = 0; hh < 3; hh++) {
                    float a = g_alpha[eid * 3 + hh];
                    s_w[t * 3 + hh] = __expf(a - s_m[hh]) * s_inv[hh];
                }
                const float4* ap = reinterpret_cast<const float4*>(eattr) + (size_t)eid * 4;
                float4* sp = reinterpret_cast<float4*>(s_ea + t * 16);
                sp[0] = ap[0]; sp[1] = ap[1]; sp[2] = ap[2]; sp[3] = ap[3];
            }
            __syncthreads();
            for (int j = 0; j < nthis; j++) {
                int src = s_src[j];
                float w = s_w[j * 3 + h];
                float2 xj = *reinterpret_cast<const float2*>(g_xproj + src * HC + c0);
                const unsigned long long* eap =
                    reinterpret_cast<const unsigned long long*>(s_ea + j * 16);
                unsigned long long e0 = 0ull, e1 = 0ull;
#pragma unroll
                for (int m = 0; m < 8; m++) {
                    unsigned long long ea = eap[m];
                    fma2(e0, ea, Wp0[m]);
                    fma2(e1, ea, Wp1[m]);
                }
                float wx0 = w * xj.x, wx1 = w * xj.y;
                fma2(acc0, e0, pk2(wx0, wx0));
                fma2(acc1, e1, pk2(wx1, wx1));
            }
            __syncthreads();
        }
        float r0 = hsum2(acc0), r1 = hsum2(acc1);
        *reinterpret_cast<float2*>(g_aggr + (size_t)i * HC + c0) = make_float2(r0, r1);
        __syncthreads();
    }
}

// ---------------- K8: out = aggr @ W_scale + bias ----------------------------
__global__ void k_out(const float* __restrict__ Ws, const float* __restrict__ bias,
                      float* __restrict__ out) {
    __shared__ __align__(16) float aT[HC * 8];  // [k][n]
    int n0 = blockIdx.x * 8;
    int t = threadIdx.x;  // 0..63 = output channel
    for (int i = t; i < 8 * HC; i += 64) {
        int n = i / HC, k = i - n * HC;
        aT[k * 8 + n] = g_aggr[(n0 + n) * HC + k];
    }
    __syncthreads();
    float acc[8];
#pragma unroll
    for (int n = 0; n < 8; n++) acc[n] = 0.f;
#pragma unroll 4
    for (int k = 0; k < HC; k++) {
        float wv = Ws[k * 64 + t];
        const float4* xr = reinterpret_cast<const float4*>(aT + k * 8);
        float4 xa = xr[0], xb = xr[1];
        acc[0] += wv * xa.x; acc[1] += wv * xa.y;
        acc[2] += wv * xa.z; acc[3] += wv * xa.w;
        acc[4] += wv * xb.x; acc[5] += wv * xb.y;
        acc[6] += wv * xb.z; acc[7] += wv * xb.w;
    }
    float b = bias[t];
#pragma unroll
    for (int n = 0; n < 8; n++) out[(n0 + n) * 64 + t] = acc[n] + b;
}

// ---------------- launch ------------------------------------------------------
extern "C" void kernel_launch(void* const* d_in, const int* in_sizes, int n_in,
                              void* d_out, int out_size) {
    const float* x     = (const float*)d_in[0];
    const int*   ei    = (const int*)d_in[1];
    const float* eattr = (const float*)d_in[2];
    const float* Wn    = (const float*)d_in[3];
    const float* We    = (const float*)d_in[4];
    const float* att   = (const float*)d_in[5];
    const float* Ws    = (const float*)d_in[6];
    const float* bias  = (const float*)d_in[7];
    float*       out   = (float*)d_out;

    k_zero<<<(N_NODES + 255) / 256, 256>>>();
    k_proj<<<N_NODES / 8, 192>>>(x, Wn);
    k_s<<<N_NODES, 192>>>(att);
    k_q<<<1, 64>>>(We, att);
    k_alpha<<<(N_EDGES + 255) / 256, 256>>>(ei, eattr);
    k_scan<<<1, 1024>>>();
    k_scatter<<<(N_EDGES + 255) / 256, 256>>>(ei);
    k_aggr<<<4096, 96>>>(ei, eattr, We);
    k_out<<<N_NODES / 8, 64>>>(Ws, bias, out);
}

// round 3
// speedup vs baseline: 1.1604x; 1.1604x over previous
#include <cuda_runtime.h>

#define N_NODES 50000
#define N_EDGES 800000
#define HEADS 3
#define HC 192
#define NEG_SLOPE 0.2f

// ---------------- scratch ------------------------------------------------------
__device__ float  g_xproj[N_NODES * HC];     // x @ W_node
__device__ float  g_sn[N_NODES * 8];         // [0..2]=s0(h), [4..6]=s2(h)
__device__ float  g_q[64];                   // folded edge-att vector (48 used)
__device__ float4 g_alpha4[N_EDGES];         // CSR-ordered logits (xyz) per edge
__device__ int    g_srcs[N_EDGES];           // CSR-ordered src node
__device__ int    g_eids[N_EDGES];           // CSR-ordered original edge id
__device__ int    g_deg[N_NODES];
__device__ int    g_rowptr[N_NODES + 1];
__device__ int    g_cursor[N_NODES];
__device__ float  g_aggr[N_NODES * HC];

// ---------------- f32x2 helpers -------------------------------------------------
__device__ __forceinline__ unsigned long long pk2(float lo, float hi) {
    unsigned long long r;
    asm("mov.b64 %0, {%1,%2};" : "=l"(r) : "f"(lo), "f"(hi));
    return r;
}
__device__ __forceinline__ void fma2(unsigned long long& d,
                                     unsigned long long a,
                                     unsigned long long b) {
    asm("fma.rn.f32x2 %0, %1, %2, %0;" : "+l"(d) : "l"(a), "l"(b));
}
__device__ __forceinline__ unsigned long long mul2(unsigned long long a,
                                                   unsigned long long b) {
    unsigned long long r;
    asm("mul.rn.f32x2 %0, %1, %2;" : "=l"(r) : "l"(a), "l"(b));
    return r;
}
__device__ __forceinline__ void unpk2(float& lo, float& hi, unsigned long long v) {
    asm("mov.b64 {%0,%1}, %2;" : "=f"(lo), "=f"(hi) : "l"(v));
}
__device__ __forceinline__ float hsum2(unsigned long long v) {
    float lo, hi; unpk2(lo, hi, v); return lo + hi;
}

// ---------------- K0: zero degree histogram -------------------------------------
__global__ void k_zero() {
    int i = blockIdx.x * blockDim.x + threadIdx.x;
    if (i < N_NODES) g_deg[i] = 0;
}

// ---------------- K1: degree histogram ------------------------------------------
__global__ void k_deg(const int* __restrict__ ei) {
    int e = blockIdx.x * blockDim.x + threadIdx.x;
    if (e < N_EDGES) atomicAdd(&g_deg[ei[N_EDGES + e]], 1);
}

// ---------------- K2: x_proj = x @ W_node, fused s0/s2 dots ---------------------
// block: 192 threads (t = output channel), 8 nodes per block.
__global__ void k_projs(const float* __restrict__ x, const float* __restrict__ Wn,
                        const float* __restrict__ att) {
    __shared__ __align__(16) float xT[64 * 8];  // [k][n]
    __shared__ float sr[6][16];
    int n0 = blockIdx.x * 8;
    int t = threadIdx.x;
    int w = t >> 5, lane = t & 31;
    int h = t >> 6, c = t & 63;
    for (int i = t; i < 8 * 64; i += 192) {
        int n = i >> 6, k = i & 63;
        xT[k * 8 + n] = x[(n0 + n) * 64 + k];
    }
    __syncthreads();
    unsigned long long acc2[4];
#pragma unroll
    for (int p = 0; p < 4; p++) acc2[p] = 0ull;
#pragma unroll 4
    for (int k = 0; k < 64; k++) {
        unsigned long long wv2 = pk2(Wn[k * HC + t], Wn[k * HC + t]);
        const unsigned long long* xr =
            reinterpret_cast<const unsigned long long*>(xT + k * 8);
#pragma unroll
        for (int p = 0; p < 4; p++) fma2(acc2[p], xr[p], wv2);
    }
    float acc[8];
#pragma unroll
    for (int p = 0; p < 4; p++) unpk2(acc[2 * p], acc[2 * p + 1], acc2[p]);
#pragma unroll
    for (int n = 0; n < 8; n++) g_xproj[(n0 + n) * HC + t] = acc[n];

    // fused s0 / s2 reduction over the 64 channels of each head
    float a0v = att[h * HC + c];
    float a2v = att[h * HC + 128 + c];
#pragma unroll
    for (int n = 0; n < 8; n++) {
        float v0 = acc[n] * a0v;
        float v2 = acc[n] * a2v;
#pragma unroll
        for (int o = 16; o; o >>= 1) {
            v0 += __shfl_xor_sync(0xffffffffu, v0, o);
            v2 += __shfl_xor_sync(0xffffffffu, v2, o);
        }
        if (lane == 0) { sr[w][n] = v0; sr[w][8 + n] = v2; }
    }
    __syncthreads();
    if (t < 48) {
        int hh = t >> 4, rem = t & 15, type = rem >> 3, n = rem & 7;
        float v = sr[2 * hh][type * 8 + n] + sr[2 * hh + 1][type * 8 + n];
        g_sn[(n0 + n) * 8 + type * 4 + hh] = v;
    }
}

// ---------------- K3: q[h,k] = sum_c W_edge[k, h*64+c] * att[h,1,c] -------------
__global__ void k_q(const float* __restrict__ We, const float* __restrict__ att) {
    int t = threadIdx.x;  // 256 threads; groups of 4 per output, 48 outputs
    int o = t >> 2, l4 = t & 3;
    float s = 0.f;
    if (o < 48) {
        int h = o >> 4, k = o & 15;
        for (int c = l4; c < 64; c += 4)
            s += We[k * HC + h * 64 + c] * att[h * HC + 64 + c];
    }
    s += __shfl_xor_sync(0xffffffffu, s, 1);
    s += __shfl_xor_sync(0xffffffffu, s, 2);
    if (o < 48 && l4 == 0) g_q[o] = s;
}

// ---------------- K4: warp-shuffle exclusive scan (rowptr, cursor) --------------
__global__ void k_scan() {
    __shared__ int s_ws[32], s_off[32], s_tot;
    int t = threadIdx.x, w = t >> 5, lane = t & 31;
    int carry = 0;
    for (int base = 0; base < N_NODES; base += 1024) {
        int i = base + t;
        int v = (i < N_NODES) ? g_deg[i] : 0;
        int incl = v;
#pragma unroll
        for (int o = 1; o < 32; o <<= 1) {
            int u = __shfl_up_sync(0xffffffffu, incl, o);
            if (lane >= o) incl += u;
        }
        if (lane == 31) s_ws[w] = incl;
        __syncthreads();
        if (w == 0) {
            int wv = s_ws[lane];
            int inc2 = wv;
#pragma unroll
            for (int o = 1; o < 32; o <<= 1) {
                int u = __shfl_up_sync(0xffffffffu, inc2, o);
                if (lane >= o) inc2 += u;
            }
            s_off[lane] = inc2 - wv;
            if (lane == 31) s_tot = inc2;
        }
        __syncthreads();
        int excl = carry + s_off[w] + incl - v;
        if (i < N_NODES) { g_rowptr[i] = excl; g_cursor[i] = excl; }
        carry += s_tot;
    }
    if (t == 0) g_rowptr[N_NODES] = carry;
}

// ---------------- K5: alpha + CSR scatter (fused) --------------------------------
__global__ void k_alpha(const int* __restrict__ ei,
                        const float* __restrict__ eattr) {
    __shared__ float qs[48];
    if (threadIdx.x < 48) qs[threadIdx.x] = g_q[threadIdx.x];
    __syncthreads();
    int e = blockIdx.x * blockDim.x + threadIdx.x;
    if (e >= N_EDGES) return;
    int src = ei[e];
    int dst = ei[N_EDGES + e];
    const float4* ap = reinterpret_cast<const float4*>(eattr) + (size_t)e * 4;
    float4 a0 = ap[0], a1 = ap[1], a2 = ap[2], a3 = ap[3];
    float al[3];
#pragma unroll
    for (int h = 0; h < 3; h++) {
        const float* q = qs + h * 16;
        float s = g_sn[dst * 8 + h] + g_sn[src * 8 + 4 + h];
        s += a0.x * q[0]  + a0.y * q[1]  + a0.z * q[2]  + a0.w * q[3];
        s += a1.x * q[4]  + a1.y * q[5]  + a1.z * q[6]  + a1.w * q[7];
        s += a2.x * q[8]  + a2.y * q[9]  + a2.z * q[10] + a2.w * q[11];
        s += a3.x * q[12] + a3.y * q[13] + a3.z * q[14] + a3.w * q[15];
        al[h] = (s >= 0.f) ? s : NEG_SLOPE * s;
    }
    int pos = atomicAdd(&g_cursor[dst], 1);
    g_alpha4[pos] = make_float4(al[0], al[1], al[2], 0.f);
    g_srcs[pos] = src;
    g_eids[pos] = e;
}

// ---------------- K6: per-node online-softmax aggregation ------------------------
// 96 threads: thread t owns channels (2t, 2t+1); head h = warp = t>>5.
#define CHUNK 32
__global__ void k_aggr(const float* __restrict__ eattr,
                       const float* __restrict__ We) {
    int t = threadIdx.x;
    int lane = t & 31;
    int c0 = 2 * t;
    int h = t >> 5;

    unsigned long long Wp0[8], Wp1[8];
#pragma unroll
    for (int m = 0; m < 8; m++) {
        Wp0[m] = pk2(We[(2 * m) * HC + c0],     We[(2 * m + 1) * HC + c0]);
        Wp1[m] = pk2(We[(2 * m) * HC + c0 + 1], We[(2 * m + 1) * HC + c0 + 1]);
    }

    __shared__ __align__(16) float s_al[CHUNK * 4];
    __shared__ float s_w[CHUNK * 4];
    __shared__ int   s_src[CHUNK];
    __shared__ __align__(16) float s_ea[4 * CHUNK * 4];  // col-major float4 [i][j]

    for (int i = blockIdx.x; i < N_NODES; i += gridDim.x) {
        int rs = g_rowptr[i], re = g_rowptr[i + 1];
        float m_run = -1e30f, z = 0.f;
        unsigned long long acc0 = 0ull, acc1 = 0ull;

        for (int base = rs; base < re; base += CHUNK) {
            int Cn = min(CHUNK, re - base);
            if (t < Cn) {
                int pos = base + t;
                float4 al = g_alpha4[pos];
                *reinterpret_cast<float4*>(s_al + t * 4) = al;
                s_src[t] = g_srcs[pos];
                int eid = g_eids[pos];
                const float4* ap =
                    reinterpret_cast<const float4*>(eattr) + (size_t)eid * 4;
#pragma unroll
                for (int q = 0; q < 4; q++)
                    *reinterpret_cast<float4*>(s_ea + (q * CHUNK + t) * 4) = ap[q];
            }
            __syncthreads();

            // per-warp (=head) online softmax update
            float a = (lane < Cn) ? s_al[lane * 4 + h] : -1e30f;
            float mloc = a;
#pragma unroll
            for (int o = 16; o; o >>= 1)
                mloc = fmaxf(mloc, __shfl_xor_sync(0xffffffffu, mloc, o));
            float m_new = fmaxf(m_run, mloc);
            float scl = __expf(m_run - m_new);
            float ex = (lane < Cn) ? __expf(a - m_new) : 0.f;
            float zl = ex;
#pragma unroll
            for (int o = 16; o; o >>= 1)
                zl += __shfl_xor_sync(0xffffffffu, zl, o);
            z = z * scl + zl;
            if (lane < Cn) s_w[lane * 4 + h] = ex;
            m_run = m_new;
            unsigned long long sclp = pk2(scl, scl);
            acc0 = mul2(acc0, sclp);
            acc1 = mul2(acc1, sclp);
            __syncwarp();

            // message accumulation over this chunk
            const float* xrow_n = g_xproj + (size_t)s_src[0] * HC + c0;
            float2 xjn = *reinterpret_cast<const float2*>(xrow_n);
            for (int j = 0; j < Cn; j++) {
                float2 xj = xjn;
                if (j + 1 < Cn)
                    xjn = *reinterpret_cast<const float2*>(
                        g_xproj + (size_t)s_src[j + 1] * HC + c0);
                float wgt = s_w[j * 4 + h];
                const unsigned long long* eap =
                    reinterpret_cast<const unsigned long long*>(s_ea);
                unsigned long long e0 = 0ull, e1 = 0ull;
#pragma unroll
                for (int m = 0; m < 8; m++) {
                    unsigned long long ea =
                        eap[((m >> 1) * CHUNK + j) * 2 + (m & 1)];
                    fma2(e0, ea, Wp0[m]);
                    fma2(e1, ea, Wp1[m]);
                }
                float wx0 = wgt * xj.x, wx1 = wgt * xj.y;
                fma2(acc0, e0, pk2(wx0, wx0));
                fma2(acc1, e1, pk2(wx1, wx1));
            }
            __syncthreads();
        }
        float inv = 1.f / (z + 1e-16f);
        float r0 = hsum2(acc0) * inv;
        float r1 = hsum2(acc1) * inv;
        *reinterpret_cast<float2*>(g_aggr + (size_t)i * HC + c0) =
            make_float2(r0, r1);
    }
}

// ---------------- K7: out = aggr @ W_scale + bias --------------------------------
__global__ void k_out(const float* __restrict__ Ws, const float* __restrict__ bias,
                      float* __restrict__ out) {
    __shared__ __align__(16) float aT[HC * 8];  // [k][n]
    int n0 = blockIdx.x * 8;
    int t = threadIdx.x;  // 0..63
    for (int i = t; i < 8 * HC; i += 64) {
        int n = i / HC, k = i - n * HC;
        aT[k * 8 + n] = g_aggr[(n0 + n) * HC + k];
    }
    __syncthreads();
    unsigned long long acc2[4];
#pragma unroll
    for (int p = 0; p < 4; p++) acc2[p] = 0ull;
#pragma unroll 4
    for (int k = 0; k < HC; k++) {
        unsigned long long wv2 = pk2(Ws[k * 64 + t], Ws[k * 64 + t]);
        const unsigned long long* ar =
            reinterpret_cast<const unsigned long long*>(aT + k * 8);
#pragma unroll
        for (int p = 0; p < 4; p++) fma2(acc2[p], ar[p], wv2);
    }
    float acc[8];
#pragma unroll
    for (int p = 0; p < 4; p++) unpk2(acc[2 * p], acc[2 * p + 1], acc2[p]);
    float b = bias[t];
#pragma unroll
    for (int n = 0; n < 8; n++) out[(n0 + n) * 64 + t] = acc[n] + b;
}

// ---------------- launch ----------------------------------------------------------
extern "C" void kernel_launch(void* const* d_in, const int* in_sizes, int n_in,
                              void* d_out, int out_size) {
    const float* x     = (const float*)d_in[0];
    const int*   ei    = (const int*)d_in[1];
    const float* eattr = (const float*)d_in[2];
    const float* Wn    = (const float*)d_in[3];
    const float* We    = (const float*)d_in[4];
    const float* att   = (const float*)d_in[5];
    const float* Ws    = (const float*)d_in[6];
    const float* bias  = (const float*)d_in[7];
    float*       out   = (float*)d_out;

    k_zero<<<(N_NODES + 255) / 256, 256>>>();
    k_deg<<<(N_EDGES + 255) / 256, 256>>>(ei);
    k_projs<<<N_NODES / 8, 192>>>(x, Wn, att);
    k_q<<<1, 256>>>(We, att);
    k_scan<<<1, 1024>>>();
    k_alpha<<<(N_EDGES + 255) / 256, 256>>>(ei, eattr);
    k_aggr<<<3072, 96>>>(eattr, We);
    k_out<<<N_NODES / 8, 64>>>(Ws, bias, out);
}